// round 6
// baseline (speedup 1.0000x reference)
#include <cuda_runtime.h>

#define BB   2
#define NN   512
#define DD   256
#define HH   4
#define HDD  64
#define HDH  256

typedef unsigned long long ull;
#define ABS2 0x7fffffff7fffffffULL

__device__ __align__(16) float g_hq[BB*NN*HDH];
__device__ __align__(16) float g_hk[BB*NN*HDH];
__device__ __align__(16) float g_hv[BB*NN*HDH];
__device__ __align__(16) float g_sq[BB*NN*HH];
__device__ __align__(16) float g_sk[BB*NN*HH];
__device__ __align__(16) float g_aa[HDD];

__device__ __forceinline__ ull add2(ull a, ull b) {
    ull r; asm("add.rn.f32x2 %0, %1, %2;" : "=l"(r) : "l"(a), "l"(b)); return r;
}
__device__ __forceinline__ ull fma2(ull a, ull b, ull c) {
    ull r; asm("fma.rn.f32x2 %0, %1, %2, %3;" : "=l"(r) : "l"(a), "l"(b), "l"(c)); return r;
}
__device__ __forceinline__ ull pack2(float lo, float hi) {
    ull r; asm("mov.b64 %0, {%1, %2};" : "=l"(r) : "f"(lo), "f"(hi)); return r;
}
__device__ __forceinline__ float2 unpack2(ull v) {
    float2 f; asm("mov.b64 {%0, %1}, %2;" : "=f"(f.x), "=f"(f.y) : "l"(v)); return f;
}

// ---------------------------------------------------------------------------
// Kernel 1: projections. Tile 16x128, 128 threads, grid = 3*64*2 = 384.
// Packed f32x2 FMA; x duplicated in smem; warp-column specialization.
// ---------------------------------------------------------------------------
__global__ __launch_bounds__(128) void proj_kernel(
    const float* __restrict__ q, const float* __restrict__ k, const float* __restrict__ v,
    const float* __restrict__ wq, const float* __restrict__ bq,
    const float* __restrict__ wv, const float* __restrict__ bv)
{
    __shared__ float sxd[2][16][36];   // [buf][k][2*16 dup rows + pad]
    __shared__ float swt[2][16][128];  // [buf][k][col]

    int bid = blockIdx.x;
    int m   = bid >> 7;            // 0=q,1=k,2=v
    int rem = bid & 127;
    int rt  = rem >> 1;            // 64 row tiles of 16
    int ct  = rem & 1;
    int r0 = rt * 16, c0 = ct * 128;

    const float* src  = (m==0) ? q : (m==1) ? k : v;
    const float* W    = (m<2)  ? wq : wv;
    const float* bias = (m<2)  ? bq : bv;
    float* dst        = (m==0) ? g_hq : (m==1) ? g_hk : g_hv;

    int tid  = threadIdx.x;
    int w    = tid >> 5;
    int lane = tid & 31;
    int rg   = lane >> 2;          // rows 2rg, 2rg+1
    int cg   = lane & 3;           // 8 cols each
    int cbase = c0 + w*32 + cg*8;

    ulonglong2 ba = *(const ulonglong2*)&bias[cbase];
    ulonglong2 bb = *(const ulonglong2*)&bias[cbase + 4];
    ull acc00 = ba.x, acc01 = ba.y, acc02 = bb.x, acc03 = bb.y;
    ull acc10 = ba.x, acc11 = ba.y, acc12 = bb.x, acc13 = bb.y;

    int xrow = tid >> 2, xkg = tid & 3;   // threads 0..63 load x

    // prefetch chunk 0
    float4 xr = make_float4(0.f,0.f,0.f,0.f);
    if (tid < 64) xr = *(const float4*)&src[(size_t)(r0 + xrow)*DD + xkg*4];
    float4 wr0 = *(const float4*)&W[(size_t)(tid>>5)*DD + c0 + (tid&31)*4];
    float4 wr1 = *(const float4*)&W[(size_t)((tid+128)>>5)*DD + c0 + (tid&31)*4];
    float4 wr2 = *(const float4*)&W[(size_t)((tid+256)>>5)*DD + c0 + (tid&31)*4];
    float4 wr3 = *(const float4*)&W[(size_t)((tid+384)>>5)*DD + c0 + (tid&31)*4];

    if (tid < 64) {
        *(ull*)&sxd[0][xkg*4+0][2*xrow] = pack2(xr.x, xr.x);
        *(ull*)&sxd[0][xkg*4+1][2*xrow] = pack2(xr.y, xr.y);
        *(ull*)&sxd[0][xkg*4+2][2*xrow] = pack2(xr.z, xr.z);
        *(ull*)&sxd[0][xkg*4+3][2*xrow] = pack2(xr.w, xr.w);
    }
    *(float4*)&swt[0][tid>>5][(tid&31)*4] = wr0;
    *(float4*)&swt[0][(tid+128)>>5][(tid&31)*4] = wr1;
    *(float4*)&swt[0][(tid+256)>>5][(tid&31)*4] = wr2;
    *(float4*)&swt[0][(tid+384)>>5][(tid&31)*4] = wr3;
    __syncthreads();

    #pragma unroll 1
    for (int c = 0; c < 16; c++) {
        int buf = c & 1;
        if (c < 15) {
            int dbase = (c + 1) * 16;
            if (tid < 64) xr = *(const float4*)&src[(size_t)(r0 + xrow)*DD + dbase + xkg*4];
            wr0 = *(const float4*)&W[(size_t)(dbase + (tid>>5))*DD + c0 + (tid&31)*4];
            wr1 = *(const float4*)&W[(size_t)(dbase + ((tid+128)>>5))*DD + c0 + (tid&31)*4];
            wr2 = *(const float4*)&W[(size_t)(dbase + ((tid+256)>>5))*DD + c0 + (tid&31)*4];
            wr3 = *(const float4*)&W[(size_t)(dbase + ((tid+384)>>5))*DD + c0 + (tid&31)*4];
        }

        #pragma unroll
        for (int kk = 0; kk < 16; kk++) {
            ulonglong2 xd  = *(const ulonglong2*)&sxd[buf][kk][4*rg];
            ulonglong2 wva = *(const ulonglong2*)&swt[buf][kk][w*32 + cg*8];
            ulonglong2 wvb = *(const ulonglong2*)&swt[buf][kk][w*32 + cg*8 + 4];
            acc00 = fma2(xd.x, wva.x, acc00);
            acc01 = fma2(xd.x, wva.y, acc01);
            acc02 = fma2(xd.x, wvb.x, acc02);
            acc03 = fma2(xd.x, wvb.y, acc03);
            acc10 = fma2(xd.y, wva.x, acc10);
            acc11 = fma2(xd.y, wva.y, acc11);
            acc12 = fma2(xd.y, wvb.x, acc12);
            acc13 = fma2(xd.y, wvb.y, acc13);
        }

        if (c < 15) {
            int nbuf = buf ^ 1;
            if (tid < 64) {
                *(ull*)&sxd[nbuf][xkg*4+0][2*xrow] = pack2(xr.x, xr.x);
                *(ull*)&sxd[nbuf][xkg*4+1][2*xrow] = pack2(xr.y, xr.y);
                *(ull*)&sxd[nbuf][xkg*4+2][2*xrow] = pack2(xr.z, xr.z);
                *(ull*)&sxd[nbuf][xkg*4+3][2*xrow] = pack2(xr.w, xr.w);
            }
            *(float4*)&swt[nbuf][tid>>5][(tid&31)*4] = wr0;
            *(float4*)&swt[nbuf][(tid+128)>>5][(tid&31)*4] = wr1;
            *(float4*)&swt[nbuf][(tid+256)>>5][(tid&31)*4] = wr2;
            *(float4*)&swt[nbuf][(tid+384)>>5][(tid&31)*4] = wr3;
        }
        __syncthreads();
    }

    size_t rowA = (size_t)(r0 + 2*rg + 0) * HDH + cbase;
    size_t rowB = (size_t)(r0 + 2*rg + 1) * HDH + cbase;
    *(ulonglong2*)&dst[rowA]     = make_ulonglong2(acc00, acc01);
    *(ulonglong2*)&dst[rowA + 4] = make_ulonglong2(acc02, acc03);
    *(ulonglong2*)&dst[rowB]     = make_ulonglong2(acc10, acc11);
    *(ulonglong2*)&dst[rowB + 4] = make_ulonglong2(acc12, acc13);
}

// ---------------------------------------------------------------------------
// Kernel 2: base scalars sq/sk + g_aa = 0.4*a
// ---------------------------------------------------------------------------
__global__ __launch_bounds__(128) void base_kernel(const float* __restrict__ a)
{
    int bid = blockIdx.x;
    if (bid == 0 && threadIdx.x < HDD) g_aa[threadIdx.x] = 0.4f * a[threadIdx.x];

    int m = bid >> 10;
    int n = bid & 1023;
    const float* hsrc = m ? g_hk : g_hq;
    float* sdst       = m ? g_sk : g_sq;

    int w = threadIdx.x >> 5, lane = threadIdx.x & 31;
    const float* row = hsrc + (size_t)n*HDH + w*HDD;
    float s = fmaf(a[lane], row[lane], a[lane+32] * row[lane+32]);
    #pragma unroll
    for (int o = 16; o; o >>= 1) s += __shfl_xor_sync(0xffffffffu, s, o);
    if (lane == 0) sdst[n*HH + w] = 0.6f * s;
}

// ---------------------------------------------------------------------------
// Kernel 3: main GAT — block per (b,h,16-row i-tile) = 256 blocks, 256 thr,
// 2 blocks/SM. hq/hv streamed in 128-row smem chunks; f split in 2 passes.
// ---------------------------------------------------------------------------
__global__ __launch_bounds__(256, 2) void gat_main(float* __restrict__ out_h,
                                                   float* __restrict__ out_e)
{
    extern __shared__ float sm[];
    float* sh_e  = sm;                    // 16*516
    float* sh_x  = sh_e + 16*516;         // 128*64 (hq chunks, then hv chunks)
    float* sh_hk = sh_x + 128*64;         // 16*68
    float* sh_sq = sh_hk + 16*68;         // 512
    float* sh_p  = sh_sq + 512;           // 16*64
    float* sh_aa = sh_p + 16*64;          // 64
    // total 19136 floats = 76544 B

    int bid = blockIdx.x;                 // b(2) * h(4) * it(32)
    int b   = bid >> 7;
    int h   = (bid >> 5) & 3;
    int i0  = (bid & 31) * 16;
    int tid = threadIdx.x;
    int lane = tid & 31;
    int wid  = tid >> 5;

    // stage hk [16 x 64] (stride 68), sq[512], aa[64]
    {
        int r = tid >> 4, fgi = tid & 15;
        float4 kv = ((const float4*)(g_hk + (size_t)(b*NN + i0 + r)*HDH + h*HDD))[fgi];
        *(float4*)&sh_hk[r*68 + fgi*4] = kv;
    }
    for (int t = tid; t < NN; t += 256)
        sh_sq[t] = g_sq[(b*NN + t)*HH + h];
    if (tid < 16) ((float4*)sh_aa)[tid] = ((const float4*)g_aa)[tid];
    __syncthreads();

    int ii = lane & 15;
    int jh = lane >> 4;
    float sk_i = g_sk[(b*NN + i0 + ii)*HH + h];

    // ---- phase A: logits over 4 hq chunks of 128 rows ----
    #pragma unroll 1
    for (int cs = 0; cs < NN; cs += 128) {
        __syncthreads();
        for (int t = tid; t < 128*16; t += 256) {
            int r = t >> 4, fgi = t & 15;
            ((float4*)sh_x)[t] =
                ((const float4*)(g_hq + (size_t)(b*NN + cs + r)*HDH + h*HDD))[fgi];
        }
        __syncthreads();

        #pragma unroll 1
        for (int pass = 0; pass < 2; pass++) {
            ull kr[16], aw[16];
            {
                const ulonglong2* kp = (const ulonglong2*)(sh_hk + ii*68 + pass*32);
                const ulonglong2* ap = (const ulonglong2*)(sh_aa + pass*32);
                #pragma unroll
                for (int g = 0; g < 8; g++) {
                    ulonglong2 kk = kp[g];
                    kr[2*g] = kk.x; kr[2*g+1] = kk.y;
                    ulonglong2 av = ap[g];
                    aw[2*g] = av.x; aw[2*g+1] = av.y;
                }
            }
            #pragma unroll 2
            for (int t = 0; t < 8; t++) {
                int jj = wid*16 + t*2 + jh;
                const ulonglong2* q2 = (const ulonglong2*)(sh_x + jj*64 + pass*32);
                ull acc0 = 0ULL, acc1 = 0ULL;
                #pragma unroll
                for (int g = 0; g < 8; g++) {
                    ulonglong2 qq = q2[g];
                    ull t0 = add2(qq.x, kr[2*g]) & ABS2;
                    acc0 = fma2(aw[2*g], t0, acc0);
                    ull t1 = add2(qq.y, kr[2*g+1]) & ABS2;
                    acc1 = fma2(aw[2*g+1], t1, acc1);
                }
                float2 a0 = unpack2(acc0), a1 = unpack2(acc1);
                float s = (a0.x + a0.y) + (a1.x + a1.y);
                int j = cs + jj;
                if (pass == 0) sh_e[ii*516 + j] = s + sk_i + sh_sq[j];
                else           sh_e[ii*516 + j] += s;
            }
        }
    }
    __syncthreads();

    // ---- phase B: row softmax (warp w -> rows 2w, 2w+1) ----
    #pragma unroll
    for (int rr = 0; rr < 2; rr++) {
        float* row = sh_e + (2*wid + rr)*516;
        float mx = -1e30f;
        for (int j = lane; j < NN; j += 32) mx = fmaxf(mx, row[j]);
        #pragma unroll
        for (int o = 16; o; o >>= 1) mx = fmaxf(mx, __shfl_xor_sync(0xffffffffu, mx, o));
        float s = 0.f;
        for (int j = lane; j < NN; j += 32) {
            float ex = __expf(row[j] - mx);
            row[j] = ex;
            s += ex;
        }
        #pragma unroll
        for (int o = 16; o; o >>= 1) s += __shfl_xor_sync(0xffffffffu, s, o);
        float inv = 1.f / s;
        for (int j = lane; j < NN; j += 32) row[j] *= inv;
    }
    __syncthreads();

    // ---- phase C1: write e [B,N,N,H] ----
    {
        float* ebase = out_e + ((size_t)(b*NN + i0) * NN) * HH + h;
        for (int t = tid; t < 16*512; t += 256) {
            int i = t >> 9, j = t & 511;
            ebase[(size_t)(i*NN + j) * HH] = sh_e[i*516 + j];
        }
    }

    // ---- phase C2: AV over 4 hv chunks; warps split j halves; smem reduce ----
    {
        int wq = wid & 3;
        int jhalf = wid >> 2;
        int r0 = 2*wq + (lane >> 4);
        int r1 = r0 + 8;
        int fg = lane & 15;

        ull a00 = 0ULL, a01 = 0ULL, a10 = 0ULL, a11 = 0ULL;

        #pragma unroll 1
        for (int cs = 0; cs < NN; cs += 128) {
            __syncthreads();
            for (int t = tid; t < 128*16; t += 256) {
                int r = t >> 4, fgi = t & 15;
                ((float4*)sh_x)[t] =
                    ((const float4*)(g_hv + (size_t)(b*NN + cs + r)*HDH + h*HDD))[fgi];
            }
            __syncthreads();

            int jb = jhalf * 64;
            #pragma unroll 2
            for (int qv = 0; qv < 64; qv += 4) {
                int jj = jb + qv;
                float4 e0 = *(const float4*)&sh_e[r0*516 + cs + jj];
                float4 e1 = *(const float4*)&sh_e[r1*516 + cs + jj];
                {
                    ulonglong2 vv = *(const ulonglong2*)(sh_x + (jj+0)*64 + fg*4);
                    ull ev0 = pack2(e0.x, e0.x), ev1 = pack2(e1.x, e1.x);
                    a00 = fma2(ev0, vv.x, a00); a01 = fma2(ev0, vv.y, a01);
                    a10 = fma2(ev1, vv.x, a10); a11 = fma2(ev1, vv.y, a11);
                }
                {
                    ulonglong2 vv = *(const ulonglong2*)(sh_x + (jj+1)*64 + fg*4);
                    ull ev0 = pack2(e0.y, e0.y), ev1 = pack2(e1.y, e1.y);
                    a00 = fma2(ev0, vv.x, a00); a01 = fma2(ev0, vv.y, a01);
                    a10 = fma2(ev1, vv.x, a10); a11 = fma2(ev1, vv.y, a11);
                }
                {
                    ulonglong2 vv = *(const ulonglong2*)(sh_x + (jj+2)*64 + fg*4);
                    ull ev0 = pack2(e0.z, e0.z), ev1 = pack2(e1.z, e1.z);
                    a00 = fma2(ev0, vv.x, a00); a01 = fma2(ev0, vv.y, a01);
                    a10 = fma2(ev1, vv.x, a10); a11 = fma2(ev1, vv.y, a11);
                }
                {
                    ulonglong2 vv = *(const ulonglong2*)(sh_x + (jj+3)*64 + fg*4);
                    ull ev0 = pack2(e0.w, e0.w), ev1 = pack2(e1.w, e1.w);
                    a00 = fma2(ev0, vv.x, a00); a01 = fma2(ev0, vv.y, a01);
                    a10 = fma2(ev1, vv.x, a10); a11 = fma2(ev1, vv.y, a11);
                }
            }
        }
        __syncthreads();
        if (jhalf == 1) {
            *(ulonglong2*)&sh_p[r0*64 + fg*4] = make_ulonglong2(a00, a01);
            *(ulonglong2*)&sh_p[r1*64 + fg*4] = make_ulonglong2(a10, a11);
        }
        __syncthreads();
        if (jhalf == 0) {
            ulonglong2 p0 = *(const ulonglong2*)&sh_p[r0*64 + fg*4];
            ulonglong2 p1 = *(const ulonglong2*)&sh_p[r1*64 + fg*4];
            a00 = add2(a00, p0.x); a01 = add2(a01, p0.y);
            a10 = add2(a10, p1.x); a11 = add2(a11, p1.y);
            float2 f0 = unpack2(a00), f1 = unpack2(a01);
            float2 f2 = unpack2(a10), f3 = unpack2(a11);
            float4 ra = make_float4(fmaxf(f0.x,0.f), fmaxf(f0.y,0.f),
                                    fmaxf(f1.x,0.f), fmaxf(f1.y,0.f));
            float4 rb = make_float4(fmaxf(f2.x,0.f), fmaxf(f2.y,0.f),
                                    fmaxf(f3.x,0.f), fmaxf(f3.y,0.f));
            *(float4*)&out_h[(size_t)(b*NN + i0 + r0)*HDH + h*HDD + fg*4] = ra;
            *(float4*)&out_h[(size_t)(b*NN + i0 + r1)*HDH + h*HDD + fg*4] = rb;
        }
    }
}

// ---------------------------------------------------------------------------
extern "C" void kernel_launch(void* const* d_in, const int* in_sizes, int n_in,
                              void* d_out, int out_size)
{
    const float* q  = (const float*)d_in[0];
    const float* k  = (const float*)d_in[1];
    const float* v  = (const float*)d_in[2];
    const float* wq = (const float*)d_in[3];
    const float* bq = (const float*)d_in[4];
    const float* wv = (const float*)d_in[5];
    const float* bv = (const float*)d_in[6];
    const float* a  = (const float*)d_in[7];

    float* out_h = (float*)d_out;
    float* out_e = out_h + (size_t)BB*NN*HDH;

    const int smem_main = (16*516 + 128*64 + 16*68 + 512 + 16*64 + 64) * (int)sizeof(float);
    cudaFuncSetAttribute(gat_main, cudaFuncAttributeMaxDynamicSharedMemorySize, smem_main);

    proj_kernel<<<384, 128>>>(q, k, v, wq, bq, wv, bv);
    base_kernel<<<2048, 128>>>(a);
    gat_main<<<256, 256, smem_main>>>(out_h, out_e);
}